// round 6
// baseline (speedup 1.0000x reference)
#include <cuda_runtime.h>
#include <math.h>
#include <stdint.h>
#include <stddef.h>

#define BDIM 16384
#define CB   8
#define KK   256
#define DD   512
#define NCOL (CB*KK)              /* 2048 */
#define NIDX (BDIM*CB)            /* 131072 */
#define NTOT ((size_t)BDIM*NCOL)  /* 33554432 per iteration */
#define NXB  1024

// ---------------- static device scratch (no allocations allowed) ----------------
static __device__ float d_X0[(size_t)BDIM*NCOL];    // x @ centers^T       (134MB)
static __device__ float d_G2[(size_t)NCOL*NCOL];    // centers @ centers^T (16MB)
static __device__ float d_Pb[(size_t)BDIM*NCOL];    // per-frame probs, last iter
static __device__ float d_gum4[(size_t)4*BDIM*NCOL];// gumbel noise, 4 iters (536MB)
static __device__ float d_censq[NCOL];
static __device__ float d_asq[NIDX];
static __device__ int   d_idx[2][NIDX];
static __device__ float d_Hb[NIDX];
static __device__ float d_ESb[NIDX];
static __device__ float d_Pc[32][NCOL];
static __device__ float d_xsqp[NXB];

// ---------------- Threefry-2x32-20 (exact JAX semantics) ----------------
__host__ __device__ __forceinline__ unsigned rotl32(unsigned x, int r) {
    return (x << r) | (x >> (32 - r));
}
__host__ __device__ __forceinline__ void tf2x32(unsigned k0, unsigned k1,
                                                unsigned& x0, unsigned& x1) {
    unsigned k2 = k0 ^ k1 ^ 0x1BD11BDAu;
    x0 += k0; x1 += k1;
#define TFR(r) { x0 += x1; x1 = rotl32(x1, (r)); x1 ^= x0; }
    TFR(13) TFR(15) TFR(26) TFR(6)   x0 += k1; x1 += k2 + 1u;
    TFR(17) TFR(29) TFR(16) TFR(24)  x0 += k2; x1 += k0 + 2u;
    TFR(13) TFR(15) TFR(26) TFR(6)   x0 += k0; x1 += k1 + 3u;
    TFR(17) TFR(29) TFR(16) TFR(24)  x0 += k1; x1 += k2 + 4u;
    TFR(13) TFR(15) TFR(26) TFR(6)   x0 += k2; x1 += k0 + 5u;
#undef TFR
}

__device__ __forceinline__ float gumbel_from_bits(unsigned r) {
    float f = __uint_as_float((r >> 9) | 0x3f800000u) - 1.0f;
    float u = (f == 0.0f) ? 1.17549435e-38f : f;
    return -logf(-logf(u));
}

// jax_threefry_partitionable random_bits: elem e -> threefry(key,(0,e)), o0^o1
__device__ __forceinline__ float gumbel_elem(unsigned k0, unsigned k1, unsigned e) {
    unsigned x0 = 0u, x1 = e;
    tf2x32(k0, k1, x0, x1);
    return gumbel_from_bits(x0 ^ x1);
}

// ---------------- cp.async helpers ----------------
__device__ __forceinline__ uint32_t smem_u32(const void* p) {
    uint32_t a;
    asm("{ .reg .u64 t; cvta.to.shared.u64 t, %1; cvt.u32.u64 %0, t; }" : "=r"(a) : "l"(p));
    return a;
}
#define CP_ASYNC16(d, s) asm volatile("cp.async.cg.shared.global [%0], [%1], 16;" :: "r"(d), "l"(s) : "memory")
#define CP_COMMIT()      asm volatile("cp.async.commit_group;" ::: "memory")
#define CP_WAIT0()       asm volatile("cp.async.wait_group 0;" ::: "memory")

// ---------------- small kernels ----------------
__global__ void init_k(const int* __restrict__ init_idx) {
    int t = blockIdx.x * blockDim.x + threadIdx.x;
    if (t < NIDX) d_idx[0][t] = init_idx[t];
}

__global__ void censq_k(const float* __restrict__ centers) {
    int row = blockIdx.x;                  // 0..2047
    const float* cc = centers + (size_t)row * DD;
    float p = 0.0f;
    for (int d = threadIdx.x; d < DD; d += 128) p = fmaf(cc[d], cc[d], p);
    #pragma unroll
    for (int off = 16; off; off >>= 1) p += __shfl_xor_sync(0xffffffffu, p, off);
    __shared__ float red[4];
    if ((threadIdx.x & 31) == 0) red[threadIdx.x >> 5] = p;
    __syncthreads();
    if (threadIdx.x == 0) d_censq[row] = ((red[0] + red[1]) + (red[2] + red[3]));
}

__global__ void xsq_k(const float* __restrict__ x) {
    const size_t N = (size_t)BDIM * DD;
    float p = 0.0f;
    for (size_t i = (size_t)blockIdx.x * blockDim.x + threadIdx.x; i < N;
         i += (size_t)gridDim.x * blockDim.x)
        p = fmaf(x[i], x[i], p);
    #pragma unroll
    for (int off = 16; off; off >>= 1) p += __shfl_xor_sync(0xffffffffu, p, off);
    __shared__ float red[8];
    if ((threadIdx.x & 31) == 0) red[threadIdx.x >> 5] = p;
    __syncthreads();
    if (threadIdx.x == 0) {
        float s = 0.0f;
        #pragma unroll
        for (int w = 0; w < 8; w++) s += red[w];
        d_xsqp[blockIdx.x] = s;
    }
}

// ---------------- GEMM tile body (byte-identical math to round 5) ----------------
__device__ __forceinline__ void gemm_body(
    const float* __restrict__ A, const float* __restrict__ centers,
    float* __restrict__ out, int bx, int cy,
    float (*As)[68], float (*Bs)[256])
{
    const int tid = threadIdx.x;
    const int w = tid >> 5, l = tid & 31;
    const int r0 = bx * 64;

    const int lr = tid >> 2, lq = tid & 3;
    const float* aP = A + (size_t)(r0 + lr) * DD + lq * 4;
    const int bk = tid >> 1, bd = (tid & 1) * 8;
    const float* b0P = centers + ((size_t)cy * KK + bk) * DD + bd;
    const float* b1P = centers + ((size_t)cy * KK + 128 + bk) * DD + bd;

    float acc[8][8];
    #pragma unroll
    for (int i = 0; i < 8; i++)
        #pragma unroll
        for (int j = 0; j < 8; j++) acc[i][j] = 0.0f;

    for (int kb = 0; kb < 32; kb++) {
        const int d0 = kb * 16;
        float4 a4 = *(const float4*)(aP + d0);
        float4 q0 = *(const float4*)(b0P + d0);
        float4 q1 = *(const float4*)(b0P + d0 + 4);
        float4 q2 = *(const float4*)(b1P + d0);
        float4 q3 = *(const float4*)(b1P + d0 + 4);
        __syncthreads();
        As[lq*4+0][lr] = a4.x; As[lq*4+1][lr] = a4.y;
        As[lq*4+2][lr] = a4.z; As[lq*4+3][lr] = a4.w;
        Bs[bd+0][bk] = q0.x; Bs[bd+1][bk] = q0.y;
        Bs[bd+2][bk] = q0.z; Bs[bd+3][bk] = q0.w;
        Bs[bd+4][bk] = q1.x; Bs[bd+5][bk] = q1.y;
        Bs[bd+6][bk] = q1.z; Bs[bd+7][bk] = q1.w;
        Bs[bd+0][128+bk] = q2.x; Bs[bd+1][128+bk] = q2.y;
        Bs[bd+2][128+bk] = q2.z; Bs[bd+3][128+bk] = q2.w;
        Bs[bd+4][128+bk] = q3.x; Bs[bd+5][128+bk] = q3.y;
        Bs[bd+6][128+bk] = q3.z; Bs[bd+7][128+bk] = q3.w;
        __syncthreads();
        #pragma unroll
        for (int d = 0; d < 16; d++) {
            float4 a0 = *(const float4*)&As[d][w*8];
            float4 a1 = *(const float4*)&As[d][w*8+4];
            float4 bb0 = *(const float4*)&Bs[d][l*8];
            float4 bb1 = *(const float4*)&Bs[d][l*8+4];
            float av[8] = {a0.x,a0.y,a0.z,a0.w,a1.x,a1.y,a1.z,a1.w};
            float bv[8] = {bb0.x,bb0.y,bb0.z,bb0.w,bb1.x,bb1.y,bb1.z,bb1.w};
            #pragma unroll
            for (int i = 0; i < 8; i++)
                #pragma unroll
                for (int j = 0; j < 8; j++)
                    acc[i][j] = fmaf(av[i], bv[j], acc[i][j]);
        }
    }

    #pragma unroll
    for (int i = 0; i < 8; i++) {
        float* o = out + (size_t)(r0 + w*8 + i) * NCOL + cy * KK + l * 8;
        float4 v0 = make_float4(acc[i][0], acc[i][1], acc[i][2], acc[i][3]);
        float4 v1 = make_float4(acc[i][4], acc[i][5], acc[i][6], acc[i][7]);
        *(float4*)o = v0;
        *(float4*)(o + 4) = v1;
    }
}

// ---------------- fused setup: X0 GEMM + G2 GEMM + 4-iter gumbel, co-resident ----------------
// 6400 blocks in groups of 25: 8 X0 tiles, 16 gumbel chunks, 1 G2 tile — interleaved
// so every scheduling wave mixes FMA-bound (GEMM) and ALU-bound (threefry) blocks.
__global__ __launch_bounds__(256, 2)
void setup_k(const float* __restrict__ x, const float* __restrict__ centers,
             float* __restrict__ X0out, float* __restrict__ G2out,
             uint4 fk0s, uint4 fk1s) {
    __shared__ float As[16][68];
    __shared__ float Bs[16][256];
    const int g = blockIdx.x / 25;
    const int r = blockIdx.x % 25;

    if (r < 8) {
        gemm_body(x, centers, X0out, g, r, As, Bs);
    } else if (r < 24) {
        const int chunk = g * 16 + (r - 8);          // 0..4095
        const int it = chunk >> 10;                  // 1024 chunks per iteration
        const unsigned kk0[4] = {fk0s.x, fk0s.y, fk0s.z, fk0s.w};
        const unsigned kk1[4] = {fk1s.x, fk1s.y, fk1s.z, fk1s.w};
        const unsigned k0 = kk0[it], k1 = kk1[it];
        const unsigned base = (unsigned)(chunk & 1023) * 32768u;
        float* dst = d_gum4 + (size_t)it * NTOT;
        const int tid = threadIdx.x;
        #pragma unroll 4
        for (int j = 0; j < 128; j++) {
            unsigned e = base + (unsigned)j * 256u + (unsigned)tid;
            dst[e] = gumbel_elem(k0, k1, e);
        }
    } else {
        gemm_body(centers, centers, G2out, g & 31, g >> 5, As, Bs);
    }
}

// ---------------- per-iteration a_sq ----------------
__global__ __launch_bounds__(256)
void asq_k(const float* __restrict__ x, const float* __restrict__ centers, int cur) {
    __shared__ float cens[CB][DD];
    __shared__ float xe[DD];
    __shared__ int ids[CB];
    const int b = blockIdx.x, tid = threadIdx.x;
    const int w = tid >> 5, l = tid & 31;
    if (tid < CB) ids[tid] = d_idx[cur][b * CB + tid];
    __syncthreads();
    for (int t = tid; t < CB * DD; t += 256) {
        int c = t >> 9, d = t & 511;
        cens[c][d] = centers[((size_t)c * KK + ids[c]) * DD + d];
    }
    __syncthreads();
    #pragma unroll
    for (int q = 0; q < 2; q++) {
        int d = tid + q * 256;
        float s = 0.0f;
        #pragma unroll
        for (int c = 0; c < CB; c++) s += cens[c][d];
        xe[d] = s - x[(size_t)b * DD + d];
    }
    __syncthreads();
    float p = 0.0f;
    #pragma unroll
    for (int it = 0; it < 16; it++) {
        int d = l + it * 32;
        float a = xe[d] - cens[w][d];
        p = fmaf(a, a, p);
    }
    #pragma unroll
    for (int off = 16; off; off >>= 1) p += __shfl_xor_sync(0xffffffffu, p, off);
    if (l == 0) d_asq[b * CB + w] = p;
}

// ---------------- fused refine: gather + combine + gumbel-argmax + stats ----------------
// dynamic smem: G2 rows[8][2048] | X0 row[2048] | censq[2048] | S[2048] | gum[2048]
#define RSM_FLOATS (12*NCOL)
__global__ void __launch_bounds__(256)
ref_k(const float* __restrict__ fes, int cur, int nxt, int last, int iter) {
    extern __shared__ float sm[];
    float* G2s = sm;                 // 8 rows
    float* X0s = sm + 8 * NCOL;
    float* CSs = sm + 9 * NCOL;
    float* Ss  = sm + 10 * NCOL;
    float* Gms = sm + 11 * NCOL;
    __shared__ int ids[CB];

    const int tid = threadIdx.x;
    const int w = tid >> 5, l = tid & 31;
    const int b = blockIdx.x;

    if (tid < CB) ids[tid] = d_idx[cur][b * CB + tid];
    __syncthreads();

    {
        #pragma unroll
        for (int c = 0; c < CB; c++) {
            const float4* src = (const float4*)(d_G2 + (size_t)(c * KK + ids[c]) * NCOL);
            uint32_t dst = smem_u32(G2s + c * NCOL);
            CP_ASYNC16(dst + tid * 16, src + tid);
            CP_ASYNC16(dst + (tid + 256) * 16, src + tid + 256);
        }
        const float4* sx = (const float4*)(d_X0 + (size_t)b * NCOL);
        uint32_t dx = smem_u32(X0s);
        CP_ASYNC16(dx + tid * 16, sx + tid);
        CP_ASYNC16(dx + (tid + 256) * 16, sx + tid + 256);
        const float4* sc = (const float4*)(d_censq);
        uint32_t dc = smem_u32(CSs);
        CP_ASYNC16(dc + tid * 16, sc + tid);
        CP_ASYNC16(dc + (tid + 256) * 16, sc + tid + 256);
        const float4* sg = (const float4*)(d_gum4 + (size_t)iter * NTOT + (size_t)b * NCOL);
        uint32_t dg = smem_u32(Gms);
        CP_ASYNC16(dg + tid * 16, sg + tid);
        CP_ASYNC16(dg + (tid + 256) * 16, sg + tid + 256);
        CP_COMMIT();
        CP_WAIT0();
    }
    __syncthreads();

    #pragma unroll
    for (int q = 0; q < 8; q++) {
        int col = tid + q * 256;
        float s = 0.0f;
        #pragma unroll
        for (int c = 0; c < CB; c++) s += G2s[c * NCOL + col];
        Ss[col] = s;
    }
    __syncthreads();

    const int c = w;
    const float asq = d_asq[b * CB + c];
    const float scale = expf(fes[0]);

    float vs[8];
    float bestS = -INFINITY; int bestK = 0;
    #pragma unroll
    for (int j = 0; j < 8; j++) {
        int k = l + 32 * j;
        int col = c * KK + k;
        float cross = (Ss[col] - X0s[col]) - G2s[c * NCOL + col];
        float v = -((asq + 2.0f * cross) + CSs[col]);   // reference grouping
        vs[j] = v;
        float g = Gms[col];
        float s = scale * v + g;
        if (s > bestS || (s == bestS && k < bestK)) { bestS = s; bestK = k; }
    }
    #pragma unroll
    for (int off = 16; off; off >>= 1) {
        float oS = __shfl_xor_sync(0xffffffffu, bestS, off);
        int   oK = __shfl_xor_sync(0xffffffffu, bestK, off);
        if (oS > bestS || (oS == bestS && oK < bestK)) { bestS = oS; bestK = oK; }
    }
    if (l == 0) d_idx[nxt][b * CB + c] = bestK;

    if (last) {
        float m = -INFINITY;
        #pragma unroll
        for (int j = 0; j < 8; j++) m = fmaxf(m, scale * vs[j]);
        #pragma unroll
        for (int off = 16; off; off >>= 1)
            m = fmaxf(m, __shfl_xor_sync(0xffffffffu, m, off));
        float se = 0.0f;
        #pragma unroll
        for (int j = 0; j < 8; j++) se += expf(scale * vs[j] - m);
        #pragma unroll
        for (int off = 16; off; off >>= 1)
            se += __shfl_xor_sync(0xffffffffu, se, off);
        float lse = m + logf(se);
        float H = 0.0f, ES = 0.0f;
        #pragma unroll
        for (int j = 0; j < 8; j++) {
            int k = l + 32 * j;
            float lp = scale * vs[j] - lse;
            float p = expf(lp);
            H  = fmaf(-p, lp, H);
            ES = fmaf(p, -vs[j], ES);
            d_Pb[(size_t)b * NCOL + c * KK + k] = p;
        }
        #pragma unroll
        for (int off = 16; off; off >>= 1) {
            H  += __shfl_xor_sync(0xffffffffu, H, off);
            ES += __shfl_xor_sync(0xffffffffu, ES, off);
        }
        if (l == 0) { d_Hb[b * CB + c] = H; d_ESb[b * CB + c] = ES; }
    }
}

// ---------------- last-iter column sums of probs (deterministic) ----------------
__global__ void colsum_k() {
    const int col = blockIdx.y * 256 + threadIdx.x;
    const int bx = blockIdx.x;             // 32 b-chunks of 512
    float s = 0.0f;
    for (int b = bx * 512; b < (bx + 1) * 512; b++)
        s += d_Pb[(size_t)b * NCOL + col];
    d_Pc[bx][col] = s;
}

// ---------------- outputs ----------------
__global__ void outidx_k(float* out, int out_size) {
    int t = blockIdx.x * blockDim.x + threadIdx.x;
    if (t < NIDX && t < out_size) out[t] = (float)d_idx[0][t];
}

__global__ void scal_k(float* out, int out_size) {
    const int t = threadIdx.x;
    __shared__ float sh[256];

    float v = 0.0f;
    for (int i = t; i < NXB; i += 256) v += d_xsqp[i];
    sh[t] = v; __syncthreads();
    for (int s = 128; s; s >>= 1) { if (t < s) sh[t] += sh[t + s]; __syncthreads(); }
    float xsq = sh[0]; __syncthreads();

    v = 0.0f;
    for (int i = t; i < NIDX; i += 256) v += d_Hb[i];
    sh[t] = v; __syncthreads();
    for (int s = 128; s; s >>= 1) { if (t < s) sh[t] += sh[t + s]; __syncthreads(); }
    float Hs = sh[0]; __syncthreads();

    v = 0.0f;
    for (int i = t; i < NIDX; i += 256) v += d_ESb[i];
    sh[t] = v; __syncthreads();
    for (int s = 128; s; s >>= 1) { if (t < s) sh[t] += sh[t + s]; __syncthreads(); }
    float ESs = sh[0]; __syncthreads();

    v = 0.0f;
    for (int col = t; col < NCOL; col += 256) {
        float s = 0.0f;
        #pragma unroll
        for (int bx = 0; bx < 32; bx++) s += d_Pc[bx][col];
        float avg = s / (float)BDIM;
        v += -avg * logf(avg + 1e-20f);
    }
    sh[t] = v; __syncthreads();
    for (int s = 128; s; s >>= 1) { if (t < s) sh[t] += sh[t + s]; __syncthreads(); }
    float cent = sh[0];

    if (t == 0 && out_size >= NIDX + 3) {
        out[NIDX + 0] = logf((float)KK) - cent / (float)CB;  // entropy_loss
        out[NIDX + 1] = Hs / (float)NIDX;                    // frame_entropy
        out[NIDX + 2] = (ESs / (float)CB) / (xsq + 1e-20f);  // reconstruction_loss
    }
}

// ---------------- launch ----------------
extern "C" void kernel_launch(void* const* d_in, const int* in_sizes, int n_in,
                              void* d_out, int out_size) {
    const float* x       = (const float*)d_in[0];
    const float* centers = (const float*)d_in[1];
    const float* fes     = (const float*)d_in[2];
    const int*   init_i  = (const int*)d_in[3];
    float* out = (float*)d_out;
    (void)in_sizes; (void)n_in;

    static int smem_set = 0;
    if (!smem_set) {
        cudaFuncSetAttribute(ref_k, cudaFuncAttributeMaxDynamicSharedMemorySize,
                             RSM_FLOATS * 4);
        smem_set = 1;
    }

    init_k<<<(NIDX + 255) / 256, 256>>>(init_i);
    censq_k<<<NCOL, 128>>>(centers);
    xsq_k<<<NXB, 256>>>(x);

    // fused: X0 = x @ CF^T, G2 = CF @ CF^T, gumbel for all 4 iterations
    {
        float* G2p; cudaGetSymbolAddress((void**)&G2p, d_G2);
        float* X0p; cudaGetSymbolAddress((void**)&X0p, d_X0);
        unsigned f0[4], f1[4];
        for (int i = 0; i < 4; i++) {
            unsigned a = 0u, b = (unsigned)i;
            tf2x32(0u, 1234u, a, b);   // fold_in(key(1234), i)
            f0[i] = a; f1[i] = b;
        }
        uint4 fk0s = make_uint4(f0[0], f0[1], f0[2], f0[3]);
        uint4 fk1s = make_uint4(f1[0], f1[1], f1[2], f1[3]);
        setup_k<<<6400, 256>>>(x, centers, X0p, G2p, fk0s, fk1s);
    }

    for (int i = 0; i < 4; i++) {
        asq_k<<<BDIM, 256>>>(x, centers, i & 1);
        ref_k<<<BDIM, 256, RSM_FLOATS * 4>>>(fes, i & 1, (i + 1) & 1,
                                             (i == 3) ? 1 : 0, i);
    }

    {
        dim3 gc(32, CB);
        colsum_k<<<gc, 256>>>();
    }
    outidx_k<<<(NIDX + 255) / 256, 256>>>(out, out_size);
    scal_k<<<1, 256>>>(out, out_size);
}

// round 7
// speedup vs baseline: 1.1753x; 1.1753x over previous
#include <cuda_runtime.h>
#include <math.h>
#include <stdint.h>
#include <stddef.h>

#define BDIM 16384
#define CB   8
#define KK   256
#define DD   512
#define NCOL (CB*KK)              /* 2048 */
#define NIDX (BDIM*CB)            /* 131072 */
#define NXB  1024

// ---------------- static device scratch (no allocations allowed) ----------------
static __device__ float d_X0[(size_t)BDIM*NCOL];   // x @ centers^T       (134MB)
static __device__ float d_G2[(size_t)NCOL*NCOL];   // centers @ centers^T (16MB)
static __device__ float d_Pb[(size_t)BDIM*NCOL];   // per-frame probs, last iter (134MB)
static __device__ float d_censq[NCOL];
static __device__ float d_asq[NIDX];
static __device__ int   d_idx[2][NIDX];
static __device__ float d_Hb[NIDX];
static __device__ float d_ESb[NIDX];
static __device__ float d_Pc[32][NCOL];
static __device__ float d_xsqp[NXB];

// ---------------- Threefry-2x32-20 (exact JAX semantics) ----------------
__host__ __device__ __forceinline__ unsigned rotl32(unsigned x, int r) {
    return (x << r) | (x >> (32 - r));
}
__host__ __device__ __forceinline__ void tf2x32(unsigned k0, unsigned k1,
                                                unsigned& x0, unsigned& x1) {
    unsigned k2 = k0 ^ k1 ^ 0x1BD11BDAu;
    x0 += k0; x1 += k1;
#define TFR(r) { x0 += x1; x1 = rotl32(x1, (r)); x1 ^= x0; }
    TFR(13) TFR(15) TFR(26) TFR(6)   x0 += k1; x1 += k2 + 1u;
    TFR(17) TFR(29) TFR(16) TFR(24)  x0 += k2; x1 += k0 + 2u;
    TFR(13) TFR(15) TFR(26) TFR(6)   x0 += k0; x1 += k1 + 3u;
    TFR(17) TFR(29) TFR(16) TFR(24)  x0 += k1; x1 += k2 + 4u;
    TFR(13) TFR(15) TFR(26) TFR(6)   x0 += k2; x1 += k0 + 5u;
#undef TFR
}

__device__ __forceinline__ float gumbel_from_bits(unsigned r) {
    float f = __uint_as_float((r >> 9) | 0x3f800000u) - 1.0f;
    float u = (f == 0.0f) ? 1.17549435e-38f : f;
    return -logf(-logf(u));
}

// jax_threefry_partitionable random_bits: elem e -> threefry(key,(0,e)), o0^o1
__device__ __forceinline__ float gumbel_elem(unsigned k0, unsigned k1, unsigned e) {
    unsigned x0 = 0u, x1 = e;
    tf2x32(k0, k1, x0, x1);
    return gumbel_from_bits(x0 ^ x1);
}

// ---------------- cp.async helpers ----------------
__device__ __forceinline__ uint32_t smem_u32(const void* p) {
    uint32_t a;
    asm("{ .reg .u64 t; cvta.to.shared.u64 t, %1; cvt.u32.u64 %0, t; }" : "=r"(a) : "l"(p));
    return a;
}
#define CP_ASYNC16(d, s) asm volatile("cp.async.cg.shared.global [%0], [%1], 16;" :: "r"(d), "l"(s) : "memory")
#define CP_COMMIT()      asm volatile("cp.async.commit_group;" ::: "memory")
#define CP_WAIT0()       asm volatile("cp.async.wait_group 0;" ::: "memory")

// ---------------- small kernels ----------------
__global__ void init_k(const int* __restrict__ init_idx) {
    int t = blockIdx.x * blockDim.x + threadIdx.x;
    if (t < NIDX) d_idx[0][t] = init_idx[t];
}

__global__ void censq_k(const float* __restrict__ centers) {
    int row = blockIdx.x;                  // 0..2047
    const float* cc = centers + (size_t)row * DD;
    float p = 0.0f;
    for (int d = threadIdx.x; d < DD; d += 128) p = fmaf(cc[d], cc[d], p);
    #pragma unroll
    for (int off = 16; off; off >>= 1) p += __shfl_xor_sync(0xffffffffu, p, off);
    __shared__ float red[4];
    if ((threadIdx.x & 31) == 0) red[threadIdx.x >> 5] = p;
    __syncthreads();
    if (threadIdx.x == 0) d_censq[row] = ((red[0] + red[1]) + (red[2] + red[3]));
}

__global__ void xsq_k(const float* __restrict__ x) {
    const size_t N = (size_t)BDIM * DD;
    float p = 0.0f;
    for (size_t i = (size_t)blockIdx.x * blockDim.x + threadIdx.x; i < N;
         i += (size_t)gridDim.x * blockDim.x)
        p = fmaf(x[i], x[i], p);
    #pragma unroll
    for (int off = 16; off; off >>= 1) p += __shfl_xor_sync(0xffffffffu, p, off);
    __shared__ float red[8];
    if ((threadIdx.x & 31) == 0) red[threadIdx.x >> 5] = p;
    __syncthreads();
    if (threadIdx.x == 0) {
        float s = 0.0f;
        #pragma unroll
        for (int w = 0; w < 8; w++) s += red[w];
        d_xsqp[blockIdx.x] = s;
    }
}

// ---------------- SGEMM with register-prefetch pipeline ----------------
// out[r][cy*256+k] = dot(A[r], centers_flat[cy*256+k]); tile 64 x 256, K(d)=512.
// Identical per-accumulator FMA order to the round-5 kernel (bit-identical output);
// only the scheduling changed: LDG for chunk kb+1 issues BEFORE compute of chunk kb,
// so the ~600cyc load latency is hidden under 1024 FFMAs instead of a barrier stall.
__global__ __launch_bounds__(256, 2)
void gemm_k(const float* __restrict__ A, const float* __restrict__ centers,
            float* __restrict__ out) {
    __shared__ float As[16][68];
    __shared__ float Bs[16][256];
    const int tid = threadIdx.x;
    const int w = tid >> 5, l = tid & 31;
    const int cy = blockIdx.y;
    const int r0 = blockIdx.x * 64;

    const int lr = tid >> 2, lq = tid & 3;
    const float* aP = A + (size_t)(r0 + lr) * DD + lq * 4;
    const int bk = tid >> 1, bd = (tid & 1) * 8;
    const float* b0P = centers + ((size_t)cy * KK + bk) * DD + bd;
    const float* b1P = centers + ((size_t)cy * KK + 128 + bk) * DD + bd;

    float acc[8][8];
    #pragma unroll
    for (int i = 0; i < 8; i++)
        #pragma unroll
        for (int j = 0; j < 8; j++) acc[i][j] = 0.0f;

    // prologue: load chunk 0
    float4 a4 = *(const float4*)(aP);
    float4 q0 = *(const float4*)(b0P);
    float4 q1 = *(const float4*)(b0P + 4);
    float4 q2 = *(const float4*)(b1P);
    float4 q3 = *(const float4*)(b1P + 4);

    for (int kb = 0; kb < 32; kb++) {
        __syncthreads();     // previous chunk's compute done; smem free
        As[lq*4+0][lr] = a4.x; As[lq*4+1][lr] = a4.y;
        As[lq*4+2][lr] = a4.z; As[lq*4+3][lr] = a4.w;
        Bs[bd+0][bk] = q0.x; Bs[bd+1][bk] = q0.y;
        Bs[bd+2][bk] = q0.z; Bs[bd+3][bk] = q0.w;
        Bs[bd+4][bk] = q1.x; Bs[bd+5][bk] = q1.y;
        Bs[bd+6][bk] = q1.z; Bs[bd+7][bk] = q1.w;
        Bs[bd+0][128+bk] = q2.x; Bs[bd+1][128+bk] = q2.y;
        Bs[bd+2][128+bk] = q2.z; Bs[bd+3][128+bk] = q2.w;
        Bs[bd+4][128+bk] = q3.x; Bs[bd+5][128+bk] = q3.y;
        Bs[bd+6][128+bk] = q3.z; Bs[bd+7][128+bk] = q3.w;
        __syncthreads();
        if (kb < 31) {       // prefetch chunk kb+1; latency hidden by compute below
            const int d0 = (kb + 1) * 16;
            a4 = *(const float4*)(aP + d0);
            q0 = *(const float4*)(b0P + d0);
            q1 = *(const float4*)(b0P + d0 + 4);
            q2 = *(const float4*)(b1P + d0);
            q3 = *(const float4*)(b1P + d0 + 4);
        }
        #pragma unroll
        for (int d = 0; d < 16; d++) {
            float4 a0 = *(const float4*)&As[d][w*8];
            float4 a1 = *(const float4*)&As[d][w*8+4];
            float4 bb0 = *(const float4*)&Bs[d][l*8];
            float4 bb1 = *(const float4*)&Bs[d][l*8+4];
            float av[8] = {a0.x,a0.y,a0.z,a0.w,a1.x,a1.y,a1.z,a1.w};
            float bv[8] = {bb0.x,bb0.y,bb0.z,bb0.w,bb1.x,bb1.y,bb1.z,bb1.w};
            #pragma unroll
            for (int i = 0; i < 8; i++)
                #pragma unroll
                for (int j = 0; j < 8; j++)
                    acc[i][j] = fmaf(av[i], bv[j], acc[i][j]);
        }
    }

    #pragma unroll
    for (int i = 0; i < 8; i++) {
        float* o = out + (size_t)(r0 + w*8 + i) * NCOL + cy * KK + l * 8;
        float4 v0 = make_float4(acc[i][0], acc[i][1], acc[i][2], acc[i][3]);
        float4 v1 = make_float4(acc[i][4], acc[i][5], acc[i][6], acc[i][7]);
        *(float4*)o = v0;
        *(float4*)(o + 4) = v1;
    }
}

// ---------------- per-iteration a_sq ----------------
__global__ __launch_bounds__(256)
void asq_k(const float* __restrict__ x, const float* __restrict__ centers, int cur) {
    __shared__ float cens[CB][DD];
    __shared__ float xe[DD];
    __shared__ int ids[CB];
    const int b = blockIdx.x, tid = threadIdx.x;
    const int w = tid >> 5, l = tid & 31;
    if (tid < CB) ids[tid] = d_idx[cur][b * CB + tid];
    __syncthreads();
    for (int t = tid; t < CB * DD; t += 256) {
        int c = t >> 9, d = t & 511;
        cens[c][d] = centers[((size_t)c * KK + ids[c]) * DD + d];
    }
    __syncthreads();
    #pragma unroll
    for (int q = 0; q < 2; q++) {
        int d = tid + q * 256;
        float s = 0.0f;
        #pragma unroll
        for (int c = 0; c < CB; c++) s += cens[c][d];
        xe[d] = s - x[(size_t)b * DD + d];
    }
    __syncthreads();
    // warp-per-codebook
    float p = 0.0f;
    #pragma unroll
    for (int it = 0; it < 16; it++) {
        int d = l + it * 32;
        float a = xe[d] - cens[w][d];
        p = fmaf(a, a, p);
    }
    #pragma unroll
    for (int off = 16; off; off >>= 1) p += __shfl_xor_sync(0xffffffffu, p, off);
    if (l == 0) d_asq[b * CB + w] = p;
}

// ---------------- fused refine: gather + combine + gumbel-argmax + stats ----------------
// dynamic smem: G2 rows[8][2048] | X0 row[2048] | censq[2048] | S[2048]
#define RSM_FLOATS (8*NCOL + 3*NCOL)
__global__ void __launch_bounds__(256)
ref_k(const float* __restrict__ fes, int cur, int nxt, int last,
      unsigned fk0, unsigned fk1) {
    extern __shared__ float sm[];
    float* G2s = sm;                 // 8 rows
    float* X0s = sm + 8 * NCOL;
    float* CSs = sm + 9 * NCOL;
    float* Ss  = sm + 10 * NCOL;
    __shared__ int ids[CB];

    const int tid = threadIdx.x;
    const int w = tid >> 5, l = tid & 31;
    const int b = blockIdx.x;

    if (tid < CB) ids[tid] = d_idx[cur][b * CB + tid];
    __syncthreads();

    // async load: 8 gathered G2 rows + X0 row + censq (2 float4 per row per thread)
    {
        #pragma unroll
        for (int c = 0; c < CB; c++) {
            const float4* src = (const float4*)(d_G2 + (size_t)(c * KK + ids[c]) * NCOL);
            uint32_t dst = smem_u32(G2s + c * NCOL);
            CP_ASYNC16(dst + tid * 16, src + tid);
            CP_ASYNC16(dst + (tid + 256) * 16, src + tid + 256);
        }
        const float4* sx = (const float4*)(d_X0 + (size_t)b * NCOL);
        uint32_t dx = smem_u32(X0s);
        CP_ASYNC16(dx + tid * 16, sx + tid);
        CP_ASYNC16(dx + (tid + 256) * 16, sx + tid + 256);
        const float4* sc = (const float4*)(d_censq);
        uint32_t dc = smem_u32(CSs);
        CP_ASYNC16(dc + tid * 16, sc + tid);
        CP_ASYNC16(dc + (tid + 256) * 16, sc + tid + 256);
        CP_COMMIT();
        CP_WAIT0();
    }
    __syncthreads();

    // S[col] = sum_{c'} G2row[c'][col], fixed order
    #pragma unroll
    for (int q = 0; q < 8; q++) {
        int col = tid + q * 256;
        float s = 0.0f;
        #pragma unroll
        for (int c = 0; c < CB; c++) s += G2s[c * NCOL + col];
        Ss[col] = s;
    }
    __syncthreads();

    // warp w handles codebook c = w; thread l handles k = l + 32*j
    const int c = w;
    const float asq = d_asq[b * CB + c];
    const float scale = expf(fes[0]);
    const unsigned ebase = ((unsigned)(b * CB + c)) << 8;

    float vs[8];
    float bestS = -INFINITY; int bestK = 0;
    #pragma unroll
    for (int j = 0; j < 8; j++) {
        int k = l + 32 * j;
        int col = c * KK + k;
        float cross = (Ss[col] - X0s[col]) - G2s[c * NCOL + col];
        float v = -((asq + 2.0f * cross) + CSs[col]);   // reference grouping
        vs[j] = v;
        float g = gumbel_elem(fk0, fk1, ebase + (unsigned)k);
        float s = scale * v + g;
        if (s > bestS || (s == bestS && k < bestK)) { bestS = s; bestK = k; }
    }
    #pragma unroll
    for (int off = 16; off; off >>= 1) {
        float oS = __shfl_xor_sync(0xffffffffu, bestS, off);
        int   oK = __shfl_xor_sync(0xffffffffu, bestK, off);
        if (oS > bestS || (oS == bestS && oK < bestK)) { bestS = oS; bestK = oK; }
    }
    if (l == 0) d_idx[nxt][b * CB + c] = bestK;

    if (last) {
        float m = -INFINITY;
        #pragma unroll
        for (int j = 0; j < 8; j++) m = fmaxf(m, scale * vs[j]);
        #pragma unroll
        for (int off = 16; off; off >>= 1)
            m = fmaxf(m, __shfl_xor_sync(0xffffffffu, m, off));
        float se = 0.0f;
        #pragma unroll
        for (int j = 0; j < 8; j++) se += expf(scale * vs[j] - m);
        #pragma unroll
        for (int off = 16; off; off >>= 1)
            se += __shfl_xor_sync(0xffffffffu, se, off);
        float lse = m + logf(se);
        float H = 0.0f, ES = 0.0f;
        #pragma unroll
        for (int j = 0; j < 8; j++) {
            int k = l + 32 * j;
            float lp = scale * vs[j] - lse;
            float p = expf(lp);
            H  = fmaf(-p, lp, H);
            ES = fmaf(p, -vs[j], ES);
            d_Pb[(size_t)b * NCOL + c * KK + k] = p;
        }
        #pragma unroll
        for (int off = 16; off; off >>= 1) {
            H  += __shfl_xor_sync(0xffffffffu, H, off);
            ES += __shfl_xor_sync(0xffffffffu, ES, off);
        }
        if (l == 0) { d_Hb[b * CB + c] = H; d_ESb[b * CB + c] = ES; }
    }
}

// ---------------- last-iter column sums of probs (deterministic) ----------------
__global__ void colsum_k() {
    const int col = blockIdx.y * 256 + threadIdx.x;
    const int bx = blockIdx.x;             // 32 b-chunks of 512
    float s = 0.0f;
    for (int b = bx * 512; b < (bx + 1) * 512; b++)
        s += d_Pb[(size_t)b * NCOL + col];
    d_Pc[bx][col] = s;
}

// ---------------- outputs ----------------
__global__ void outidx_k(float* out, int out_size) {
    int t = blockIdx.x * blockDim.x + threadIdx.x;
    if (t < NIDX && t < out_size) out[t] = (float)d_idx[0][t];
}

__global__ void scal_k(float* out, int out_size) {
    const int t = threadIdx.x;
    __shared__ float sh[256];

    float v = 0.0f;
    for (int i = t; i < NXB; i += 256) v += d_xsqp[i];
    sh[t] = v; __syncthreads();
    for (int s = 128; s; s >>= 1) { if (t < s) sh[t] += sh[t + s]; __syncthreads(); }
    float xsq = sh[0]; __syncthreads();

    v = 0.0f;
    for (int i = t; i < NIDX; i += 256) v += d_Hb[i];
    sh[t] = v; __syncthreads();
    for (int s = 128; s; s >>= 1) { if (t < s) sh[t] += sh[t + s]; __syncthreads(); }
    float Hs = sh[0]; __syncthreads();

    v = 0.0f;
    for (int i = t; i < NIDX; i += 256) v += d_ESb[i];
    sh[t] = v; __syncthreads();
    for (int s = 128; s; s >>= 1) { if (t < s) sh[t] += sh[t + s]; __syncthreads(); }
    float ESs = sh[0]; __syncthreads();

    v = 0.0f;
    for (int col = t; col < NCOL; col += 256) {
        float s = 0.0f;
        #pragma unroll
        for (int bx = 0; bx < 32; bx++) s += d_Pc[bx][col];
        float avg = s / (float)BDIM;
        v += -avg * logf(avg + 1e-20f);
    }
    sh[t] = v; __syncthreads();
    for (int s = 128; s; s >>= 1) { if (t < s) sh[t] += sh[t + s]; __syncthreads(); }
    float cent = sh[0];

    if (t == 0 && out_size >= NIDX + 3) {
        out[NIDX + 0] = logf((float)KK) - cent / (float)CB;  // entropy_loss
        out[NIDX + 1] = Hs / (float)NIDX;                    // frame_entropy
        out[NIDX + 2] = (ESs / (float)CB) / (xsq + 1e-20f);  // reconstruction_loss
    }
}

// ---------------- launch ----------------
extern "C" void kernel_launch(void* const* d_in, const int* in_sizes, int n_in,
                              void* d_out, int out_size) {
    const float* x       = (const float*)d_in[0];
    const float* centers = (const float*)d_in[1];
    const float* fes     = (const float*)d_in[2];
    const int*   init_i  = (const int*)d_in[3];
    float* out = (float*)d_out;
    (void)in_sizes; (void)n_in;

    static int smem_set = 0;
    if (!smem_set) {
        cudaFuncSetAttribute(ref_k, cudaFuncAttributeMaxDynamicSharedMemorySize,
                             RSM_FLOATS * 4);
        smem_set = 1;
    }

    init_k<<<(NIDX + 255) / 256, 256>>>(init_i);
    censq_k<<<NCOL, 128>>>(centers);
    xsq_k<<<NXB, 256>>>(x);

    // one-time GEMMs: G2 = CF @ CF^T, X0 = x @ CF^T
    {
        float* G2p; cudaGetSymbolAddress((void**)&G2p, d_G2);
        float* X0p; cudaGetSymbolAddress((void**)&X0p, d_X0);
        dim3 gg(NCOL / 64, CB);
        gemm_k<<<gg, 256>>>(centers, centers, G2p);
        dim3 gx(BDIM / 64, CB);
        gemm_k<<<gx, 256>>>(x, centers, X0p);
    }

    for (int i = 0; i < 4; i++) {
        unsigned fk0 = 0u, fk1 = (unsigned)i;
        tf2x32(0u, 1234u, fk0, fk1);   // fold_in(key(1234), i)
        asq_k<<<BDIM, 256>>>(x, centers, i & 1);
        ref_k<<<BDIM, 256, RSM_FLOATS * 4>>>(fes, i & 1, (i + 1) & 1,
                                             (i == 3) ? 1 : 0, fk0, fk1);
    }

    {
        dim3 gc(32, CB);
        colsum_k<<<gc, 256>>>();
    }
    outidx_k<<<(NIDX + 255) / 256, 256>>>(out, out_size);
    scal_k<<<1, 256>>>(out, out_size);
}